// round 1
// baseline (speedup 1.0000x reference)
#include <cuda_runtime.h>
#include <cuda_bf16.h>
#include <cstdint>

// Capsule routing: B=2048, R=64, H=512, NUM_ITER=3.
// Output: final_vec [B, H] float32.
//
// Collapsed algorithm (b_ij accumulates x * v):
//   s0 = mean_r x;               v1 = squash(s0)
//   softmax_r(x * v1)        ->  v2 = squash(sum_r c x)
//   softmax_r(x * (v1+v2))   ->  v3 = squash(sum_r c x)   -> output v3
//
// squash(s) = s * sqrt(norm)/(1+sqrt(norm)),  norm = sum_h s^2  (per batch).
//
// Layout: one CTA per batch, one thread per h. Each thread keeps its
// 64-element column in registers (input read exactly once from HBM,
// perfectly coalesced across the warp since h is the fast dim).

#define B_DIM 2048
#define R_DIM 64
#define H_DIM 512

__device__ __forceinline__ float fast_exp2(float x) {
    float r;
    asm("ex2.approx.ftz.f32 %0, %1;" : "=f"(r) : "f"(x));
    return r;
}

// Block-wide sum over 512 threads (16 warps). Returns result to all threads.
__device__ __forceinline__ float block_sum(float val, float* sred) {
    #pragma unroll
    for (int o = 16; o > 0; o >>= 1)
        val += __shfl_xor_sync(0xffffffffu, val, o);
    int wid = threadIdx.x >> 5;
    int lid = threadIdx.x & 31;
    __syncthreads();                 // protect sred reuse across calls
    if (lid == 0) sred[wid] = val;
    __syncthreads();
    if (threadIdx.x < 32) {
        float v = (lid < 16) ? sred[lid] : 0.0f;
        #pragma unroll
        for (int o = 8; o > 0; o >>= 1)
            v += __shfl_xor_sync(0xffffffffu, v, o);
        if (lid == 0) sred[0] = v;
    }
    __syncthreads();
    return sred[0];
}

__global__ void __launch_bounds__(H_DIM, 1)
capsule_kernel(const float* __restrict__ x, float* __restrict__ out) {
    __shared__ float sred[32];

    const int b = blockIdx.x;
    const int h = threadIdx.x;

    const float* xb = x + (size_t)b * (R_DIM * H_DIM) + h;

    // ---- Load column into registers; fused sum / max / min pass ----
    float xr[R_DIM];
    float sum0 = 0.0f;
    float xmax = -3.402823466e38f;
    float xmin =  3.402823466e38f;
    #pragma unroll
    for (int r = 0; r < R_DIM; r++) {
        xr[r] = __ldg(xb + r * H_DIM);
        sum0 += xr[r];
        xmax = fmaxf(xmax, xr[r]);
        xmin = fminf(xmin, xr[r]);
    }

    // ---- iter 0: uniform coefficients -> mean over r, then squash ----
    float s = sum0 * (1.0f / (float)R_DIM);
    float norm = block_sum(s * s, sred);
    float sq = sqrtf(norm);
    float f  = sq / (1.0f + sq);
    float v  = f * s;       // v1 (this thread's h component)
    float w  = v;           // accumulated routing weight for logits

    const float L2E = 1.4426950408889634f;

    // ---- iterations 1 and 2 ----
    #pragma unroll
    for (int it = 0; it < 2; it++) {
        // softmax over r of logits x_r * w, in base-2 domain
        float wl = w * L2E;
        float m  = fmaxf(wl * xmax, wl * xmin);   // max_r(x_r * wl)
        float se  = 0.0f;
        float sex = 0.0f;
        #pragma unroll
        for (int r = 0; r < R_DIM; r++) {
            float e = fast_exp2(fmaf(xr[r], wl, -m));
            se += e;
            sex = fmaf(e, xr[r], sex);
        }
        s = sex / se;                              // sum_r c_r x_r

        norm = block_sum(s * s, sred);
        sq = sqrtf(norm);
        f  = sq / (1.0f + sq);
        v  = f * s;
        w += v;                                    // b_ij accumulation for next iter
    }

    out[(size_t)b * H_DIM + h] = v;
}

extern "C" void kernel_launch(void* const* d_in, const int* in_sizes, int n_in,
                              void* d_out, int out_size) {
    const float* x = (const float*)d_in[0];
    float* out = (float*)d_out;
    capsule_kernel<<<B_DIM, H_DIM>>>(x, out);
}